// round 1
// baseline (speedup 1.0000x reference)
#include <cuda_runtime.h>
#include <math.h>

// MaskedHeteroGAT collapses analytically:
//   Layer-2 source features are zeros -> xl2 = 0 -> aggregated output = 0
//   -> h2[t] = broadcast(b2[t]); s[t] rows all equal p_t = softmax(b2[t] @ Ws[t]).
//   link_t = sqrt(E - 2E/C + (N^2/C) * sum_j p_j^2) / N^2
//   ent    = (sum_t ent(p_t) + ent_pkg) / 7,  ent_pkg = -log(1/C + 1e-15)
//   out    = sum_t link_t + ent
//
// Inputs (metadata order):
//   [0..6]  x_pkg, x_path, x_dns, x_cmd, x_ip, x_port, x_host   (N*128 each)
//   [7..12] ei_path..ei_host                                    (2*E each)
//   [13] Wl1  [14] Wr1  [15] a1  [16] b1
//   [17] Wl2  [18] Wr2  [19] a2  [20] b2 (6*128)  [21] Ws (6*128*64)

#define T_TYPES 6
#define HD      128
#define CC      64

__global__ void collapsed_hgat_kernel(const float* __restrict__ b2,
                                      const float* __restrict__ Ws,
                                      float* __restrict__ out,
                                      float fN, float fE)
{
    __shared__ float z[T_TYPES][CC];
    __shared__ double sumsq_s[T_TYPES];
    __shared__ double ent_s[T_TYPES];

    const int tid = threadIdx.x;

    // Stage 1: z[t][j] = sum_k b2[t*HD + k] * Ws[t*HD*CC + k*CC + j]
    if (tid < T_TYPES * CC) {
        const int t = tid / CC;
        const int j = tid % CC;
        const float* __restrict__ b = b2 + t * HD;
        const float* __restrict__ W = Ws + (size_t)t * HD * CC + j;
        float acc = 0.0f;
        #pragma unroll 8
        for (int k = 0; k < HD; ++k) {
            acc = fmaf(b[k], W[(size_t)k * CC], acc);
        }
        z[t][j] = acc;
    }
    __syncthreads();

    // Stage 2: one thread per type does the 64-wide softmax + stats (trivial work)
    if (tid < T_TYPES) {
        float m = -1e30f;
        #pragma unroll
        for (int j = 0; j < CC; ++j) m = fmaxf(m, z[tid][j]);

        float e[CC];
        double s = 0.0;
        #pragma unroll
        for (int j = 0; j < CC; ++j) {
            e[j] = expf(z[tid][j] - m);
            s += (double)e[j];
        }
        const double inv_s = 1.0 / s;
        double sumsq = 0.0, ent = 0.0;
        #pragma unroll
        for (int j = 0; j < CC; ++j) {
            double p = (double)e[j] * inv_s;
            sumsq += p * p;
            ent   -= p * log(p + 1e-15);
        }
        sumsq_s[tid] = sumsq;
        ent_s[tid]   = ent;
    }
    __syncthreads();

    // Stage 3: combine on thread 0
    if (tid == 0) {
        const double N  = (double)fN;
        const double E  = (double)fE;
        const double C  = (double)CC;
        const double N2 = N * N;

        double link = 0.0;
        double ent_sum = 0.0;
        #pragma unroll
        for (int t = 0; t < T_TYPES; ++t) {
            double v = E - 2.0 * E / C + (N2 / C) * sumsq_s[t];
            if (v < 0.0) v = 0.0;
            link += sqrt(v) / N2;
            ent_sum += ent_s[t];
        }
        const double ent_pkg = -log(1.0 / C + 1e-15);
        const double ent = (ent_sum + ent_pkg) / 7.0;

        out[0] = (float)(link + ent);
    }
}

extern "C" void kernel_launch(void* const* d_in, const int* in_sizes, int n_in,
                              void* d_out, int out_size)
{
    const float* b2 = (const float*)d_in[20];   // [6, 128]
    const float* Ws = (const float*)d_in[21];   // [6, 128, 64]

    const float fN = (float)(in_sizes[0] / HD);     // nodes per type (20000)
    const float fE = (float)(in_sizes[7] / 2);      // edges per type (200000)

    collapsed_hgat_kernel<<<1, T_TYPES * CC>>>(b2, Ws, (float*)d_out, fN, fE);
}